// round 4
// baseline (speedup 1.0000x reference)
#include <cuda_runtime.h>
#include <stdint.h>
#include <math.h>

// Problem constants (SHAPE = (16,1,1024,1024), RATIO = 0.25)
#define N_TOTAL   16777216
#define N_VEC     (N_TOTAL / 4)
#define K_SEL     4194304
#define H1_BINS   8192       // bits [30:18] (sign always 0 since loss >= 0)
#define H2_BINS   262144     // bits [17:0]  -> exact value within coarse bucket
#define GRID_BIG  304
#define TPB_BIG   1024

// Scratch state (device globals -- no allocation allowed)
__device__ uint32_t g_scratch[N_TOTAL];   // loss as ordered uint32 bit patterns
__device__ uint32_t g_hist1[H1_BINS];
__device__ uint32_t g_hist2[H2_BINS];
__device__ uint32_t g_bstar;
__device__ uint32_t g_cAbove;
__device__ double   g_sumAbove;

__device__ __forceinline__ float bce_loss(float x, float t) {
    // max(x,0) - x*t + log1p(exp(-|x|)); always >= 0 for t in [0,1)
    float l = fmaxf(x, 0.0f) - x * t + log1pf(__expf(-fabsf(x)));
    return fmaxf(l, 0.0f);  // defensive: keep sign bit 0 so uint order == float order
}

// ---------------------------------------------------------------------------
// K0: zero the histograms + accumulator (must run every graph replay)
// ---------------------------------------------------------------------------
__global__ void zero_kernel() {
    int idx = blockIdx.x * blockDim.x + threadIdx.x;
    int stride = gridDim.x * blockDim.x;
    for (int i = idx; i < H2_BINS; i += stride) g_hist2[i] = 0u;
    for (int i = idx; i < H1_BINS; i += stride) g_hist1[i] = 0u;
    if (idx == 0) g_sumAbove = 0.0;
}

// ---------------------------------------------------------------------------
// K1: compute loss, write scratch, build coarse 8192-bin histogram
// ---------------------------------------------------------------------------
__device__ __forceinline__ void hist_add(uint32_t* sh, uint32_t v, unsigned lane) {
    uint32_t bin = v >> 18;                       // < 8192 for any non-negative float
    unsigned m = __match_any_sync(0xFFFFFFFFu, bin);  // warp-aggregate hot bins
    unsigned leader = __ffs(m) - 1u;
    if (lane == leader) atomicAdd(&sh[bin], (uint32_t)__popc(m));
}

__global__ void __launch_bounds__(TPB_BIG) loss_hist_kernel(
    const float* __restrict__ pred, const float* __restrict__ tgt) {
    __shared__ uint32_t sh[H1_BINS];              // 32 KB
    for (int i = threadIdx.x; i < H1_BINS; i += TPB_BIG) sh[i] = 0u;
    __syncthreads();

    unsigned lane = threadIdx.x & 31u;
    int tid = blockIdx.x * TPB_BIG + threadIdx.x;
    int stride = gridDim.x * TPB_BIG;
    const float4* p4 = (const float4*)pred;
    const float4* t4 = (const float4*)tgt;
    uint4* s4 = (uint4*)g_scratch;

    // N_VEC and stride are multiples of 32 -> loop trip count is warp-uniform,
    // so the full-mask __match_any_sync is legal.
    for (int i = tid; i < N_VEC; i += stride) {
        float4 p = p4[i];
        float4 t = t4[i];
        uint4 u;
        u.x = __float_as_uint(bce_loss(p.x, t.x));
        u.y = __float_as_uint(bce_loss(p.y, t.y));
        u.z = __float_as_uint(bce_loss(p.z, t.z));
        u.w = __float_as_uint(bce_loss(p.w, t.w));
        s4[i] = u;
        hist_add(sh, u.x, lane);
        hist_add(sh, u.y, lane);
        hist_add(sh, u.z, lane);
        hist_add(sh, u.w, lane);
    }
    __syncthreads();
    for (int i = threadIdx.x; i < H1_BINS; i += TPB_BIG) {
        uint32_t c = sh[i];
        if (c) atomicAdd(&g_hist1[i], c);
    }
}

// ---------------------------------------------------------------------------
// K2: single block -- find coarse bucket b* containing the K-th largest
// ---------------------------------------------------------------------------
__global__ void __launch_bounds__(1024) select_bucket_kernel() {
    __shared__ uint32_t csum[1024];
    __shared__ uint32_t wsum[32];
    int t = threadIdx.x;
    uint32_t s = 0;
    int base = t * 8;                    // 8 bins per thread
#pragma unroll
    for (int j = 0; j < 8; j++) s += g_hist1[base + j];
    csum[t] = s;
    uint32_t ws = s;
#pragma unroll
    for (int o = 16; o; o >>= 1) ws += __shfl_down_sync(0xFFFFFFFFu, ws, o);
    if ((t & 31) == 0) wsum[t >> 5] = ws;
    __syncthreads();

    if (t == 0) {
        uint32_t cum = 0;
        int w = 31;
        for (; w >= 0; w--) { if (cum + wsum[w] >= (uint32_t)K_SEL) break; cum += wsum[w]; }
        int c = w * 32 + 31;
        for (; c >= w * 32; c--) { if (cum + csum[c] >= (uint32_t)K_SEL) break; cum += csum[c]; }
        int b = c * 8 + 7;
        for (; b >= c * 8; b--) {
            uint32_t h = g_hist1[b];
            if (cum + h >= (uint32_t)K_SEL) break;
            cum += h;
        }
        g_bstar = (uint32_t)b;
        g_cAbove = cum;                  // count of elements strictly above bucket b*
    }
}

// ---------------------------------------------------------------------------
// K3: sum elements above bucket b*; exact-value histogram inside bucket b*
// ---------------------------------------------------------------------------
__global__ void __launch_bounds__(TPB_BIG) refine_kernel() {
    const uint32_t bstar = g_bstar;
    int tid = blockIdx.x * TPB_BIG + threadIdx.x;
    int stride = gridDim.x * TPB_BIG;
    const uint4* s4 = (const uint4*)g_scratch;
    float fs = 0.0f;

    for (int i = tid; i < N_VEC; i += stride) {
        uint4 u = s4[i];
        uint32_t v, b;
        v = u.x; b = v >> 18;
        if (b > bstar) fs += __uint_as_float(v);
        else if (b == bstar) atomicAdd(&g_hist2[v & 0x3FFFFu], 1u);
        v = u.y; b = v >> 18;
        if (b > bstar) fs += __uint_as_float(v);
        else if (b == bstar) atomicAdd(&g_hist2[v & 0x3FFFFu], 1u);
        v = u.z; b = v >> 18;
        if (b > bstar) fs += __uint_as_float(v);
        else if (b == bstar) atomicAdd(&g_hist2[v & 0x3FFFFu], 1u);
        v = u.w; b = v >> 18;
        if (b > bstar) fs += __uint_as_float(v);
        else if (b == bstar) atomicAdd(&g_hist2[v & 0x3FFFFu], 1u);
    }

    __shared__ float wpart[32];
#pragma unroll
    for (int o = 16; o; o >>= 1) fs += __shfl_down_sync(0xFFFFFFFFu, fs, o);
    if ((threadIdx.x & 31) == 0) wpart[threadIdx.x >> 5] = fs;
    __syncthreads();
    if (threadIdx.x == 0) {
        double d = 0.0;
#pragma unroll
        for (int i = 0; i < 32; i++) d += (double)wpart[i];
        atomicAdd(&g_sumAbove, d);
    }
}

// ---------------------------------------------------------------------------
// K4: single block -- exact threshold, tie handling, final mean
// ---------------------------------------------------------------------------
__global__ void __launch_bounds__(1024) finalize_kernel(float* __restrict__ out) {
    __shared__ uint32_t csum[1024];
    __shared__ uint32_t wsum[32];
    __shared__ double   dpart[32];
    __shared__ uint32_t s_binT, s_need;

    int t = threadIdx.x;
    const uint32_t bstar = g_bstar;
    const uint32_t rem = (uint32_t)K_SEL - g_cAbove;   // 1 <= rem <= hist1[b*]
    int base = t * 256;                                // 256 bins per thread

    uint32_t s = 0;
    for (int j = 0; j < 256; j++) s += g_hist2[base + j];
    csum[t] = s;
    uint32_t ws = s;
#pragma unroll
    for (int o = 16; o; o >>= 1) ws += __shfl_down_sync(0xFFFFFFFFu, ws, o);
    if ((t & 31) == 0) wsum[t >> 5] = ws;
    __syncthreads();

    if (t == 0) {
        uint32_t cum = 0;
        int w = 31;
        for (; w >= 0; w--) { if (cum + wsum[w] >= rem) break; cum += wsum[w]; }
        int c = w * 32 + 31;
        for (; c >= w * 32; c--) { if (cum + csum[c] >= rem) break; cum += csum[c]; }
        int b = c * 256 + 255;
        for (; b >= c * 256; b--) {
            uint32_t h = g_hist2[b];
            if (cum + h >= rem) break;
            cum += h;
        }
        s_binT = (uint32_t)b;
        s_need = rem - cum;              // # of elements equal to threshold to include
    }
    __syncthreads();

    const uint32_t binT = s_binT;
    // Sum of in-bucket elements strictly above threshold: bins are exact values.
    double ds = 0.0;
    for (int j = 0; j < 256; j++) {
        uint32_t b = (uint32_t)(base + j);
        if (b > binT) {
            uint32_t h = g_hist2[b];
            if (h) ds += (double)h * (double)__uint_as_float((bstar << 18) | b);
        }
    }
#pragma unroll
    for (int o = 16; o; o >>= 1) ds += __shfl_down_sync(0xFFFFFFFFu, ds, o);
    if ((t & 31) == 0) dpart[t >> 5] = ds;
    __syncthreads();

    if (t == 0) {
        double tot = g_sumAbove;
#pragma unroll
        for (int i = 0; i < 32; i++) tot += dpart[i];
        float tval = __uint_as_float((bstar << 18) | binT);
        tot += (double)s_need * (double)tval;
        out[0] = (float)(tot / (double)K_SEL);
    }
}

// ---------------------------------------------------------------------------
extern "C" void kernel_launch(void* const* d_in, const int* in_sizes, int n_in,
                              void* d_out, int out_size) {
    (void)in_sizes; (void)n_in; (void)out_size;
    const float* pred = (const float*)d_in[0];
    const float* tgt  = (const float*)d_in[1];
    float* out = (float*)d_out;

    zero_kernel<<<256, 1024>>>();
    loss_hist_kernel<<<GRID_BIG, TPB_BIG>>>(pred, tgt);
    select_bucket_kernel<<<1, 1024>>>();
    refine_kernel<<<GRID_BIG, TPB_BIG>>>();
    finalize_kernel<<<1, 1024>>>(out);
}

// round 5
// speedup vs baseline: 2.5805x; 2.5805x over previous
#include <cuda_runtime.h>
#include <stdint.h>

// Problem constants (SHAPE = (16,1,1024,1024), RATIO = 0.25)
#define N_TOTAL   16777216
#define N_VEC     (N_TOTAL / 4)
#define K_SEL     4194304u
#define GRID_BIG  304
#define TPB       1024
#define FULL      0xFFFFFFFFu

// Device-global scratch (no allocation allowed)
__device__ uint32_t g_scratch[N_TOTAL];   // loss as ordered uint32 bit patterns
__device__ uint32_t g_cnt[4][32];         // per-level 32-way radix counts
__device__ double   g_sumAbove;

// ---------------------------------------------------------------------------
__device__ __forceinline__ float bce_loss(float x, float t) {
    // max(x,0) - x*t + log1p(exp(-|x|)); always >= 0 for t in [0,1)
    float e = __expf(-fabsf(x));
    float l = fmaxf(x, 0.0f) - x * t + __logf(1.0f + e);
    return fmaxf(l, 0.0f);   // keep sign bit 0 -> uint order == float order
}

struct LaneMasks { uint32_t e0, e1, e2, e3, e4; };
__device__ __forceinline__ LaneMasks make_masks(uint32_t lane) {
    LaneMasks m;
    m.e0 = (lane & 1u)  ? 0u : FULL;
    m.e1 = (lane & 2u)  ? 0u : FULL;
    m.e2 = (lane & 4u)  ? 0u : FULL;
    m.e3 = (lane & 8u)  ? 0u : FULL;
    m.e4 = (lane & 16u) ? 0u : FULL;
    return m;
}

// Exact 32-bin count of one element-per-lane batch via 6 ballots.
// Lane L accumulates the count of elements whose bits[shift+4:shift] == L
// (restricted to lanes with inb). Must be called warp-uniformly.
__device__ __forceinline__ void ballot_count(uint32_t v, bool inb, int shift,
                                             const LaneMasks& e, uint32_t& cnt) {
    unsigned bb = __ballot_sync(FULL, inb);
    unsigned b0 = __ballot_sync(FULL, inb && ((v >> (shift + 0)) & 1u));
    unsigned b1 = __ballot_sync(FULL, inb && ((v >> (shift + 1)) & 1u));
    unsigned b2 = __ballot_sync(FULL, inb && ((v >> (shift + 2)) & 1u));
    unsigned b3 = __ballot_sync(FULL, inb && ((v >> (shift + 3)) & 1u));
    unsigned b4 = __ballot_sync(FULL, inb && ((v >> (shift + 4)) & 1u));
    unsigned m = ((b0 ^ e.e0) & (b1 ^ e.e1)) &
                 ((b2 ^ e.e2) & (b3 ^ e.e3)) &
                 ((b4 ^ e.e4) & bb);
    cnt += __popc(m);
}

// Warp-parallel descending-rank bucket pick over a 32-count row.
// Finds b s.t. sum_{j>b} row[j] < kr <= sum_{j>=b} row[j].
__device__ __forceinline__ void warp_pick(const uint32_t* __restrict__ row,
                                          uint32_t kr, uint32_t lane,
                                          uint32_t& b, uint32_t& above) {
    uint32_t c = row[lane];
    uint32_t x = c;                                   // suffix inclusive scan
#pragma unroll
    for (int off = 1; off < 32; off <<= 1) {
        uint32_t y = __shfl_down_sync(FULL, x, off);
        if (lane + off < 32) x += y;
    }
    uint32_t ab = x - c;                              // sum over j > lane
    unsigned m = __ballot_sync(FULL, (ab < kr) && (ab + c >= kr));
    b = (uint32_t)(__ffs(m) - 1);
    above = __shfl_sync(FULL, ab, b);
}

// Replay `levels` bucket picks; returns 5*levels-bit prefix and residual rank.
__device__ __forceinline__ void chain(int levels, uint32_t lane,
                                      uint32_t& prefix, uint32_t& kr,
                                      uint32_t& lastB) {
    prefix = 0u; kr = K_SEL; lastB = 0u;
    for (int l = 0; l < levels; l++) {
        uint32_t b, ab;
        warp_pick(g_cnt[l], kr, lane, b, ab);
        prefix = (prefix << 5) | b;
        kr -= ab;
        lastB = b;
    }
}

// ---------------------------------------------------------------------------
// K0: zero counters + accumulator (every graph replay)
// ---------------------------------------------------------------------------
__global__ void kzero() {
    int t = threadIdx.x;
    if (t < 128) ((uint32_t*)g_cnt)[t] = 0u;
    if (t == 0)  g_sumAbove = 0.0;
}

// ---------------------------------------------------------------------------
// K1: compute loss, write scratch, level-1 count on bits[30:26] (no atomics
// in the hot loop; one block-aggregated atomic per bin at the end)
// ---------------------------------------------------------------------------
__global__ void __launch_bounds__(TPB) k1_loss(const float* __restrict__ pred,
                                               const float* __restrict__ tgt) {
    __shared__ uint32_t sh[32];
    if (threadIdx.x < 32) sh[threadIdx.x] = 0u;
    __syncthreads();

    const uint32_t lane = threadIdx.x & 31u;
    const LaneMasks e = make_masks(lane);
    uint32_t cnt = 0;

    int tid = blockIdx.x * TPB + threadIdx.x;
    const int stride = GRID_BIG * TPB;
    const float4* p4 = (const float4*)pred;
    const float4* t4 = (const float4*)tgt;
    uint4* s4 = (uint4*)g_scratch;

    // stride and N_VEC are multiples of 32 -> all guards are warp-uniform.
    for (int i = tid; i < N_VEC; i += 2 * stride) {
        float4 pa = p4[i], ta = t4[i];
        bool sec = (i + stride) < N_VEC;
        float4 pb, tb;
        if (sec) { pb = p4[i + stride]; tb = t4[i + stride]; }

        uint4 u;
        u.x = __float_as_uint(bce_loss(pa.x, ta.x));
        u.y = __float_as_uint(bce_loss(pa.y, ta.y));
        u.z = __float_as_uint(bce_loss(pa.z, ta.z));
        u.w = __float_as_uint(bce_loss(pa.w, ta.w));
        s4[i] = u;
        ballot_count(u.x, true, 26, e, cnt);
        ballot_count(u.y, true, 26, e, cnt);
        ballot_count(u.z, true, 26, e, cnt);
        ballot_count(u.w, true, 26, e, cnt);

        if (sec) {
            uint4 w;
            w.x = __float_as_uint(bce_loss(pb.x, tb.x));
            w.y = __float_as_uint(bce_loss(pb.y, tb.y));
            w.z = __float_as_uint(bce_loss(pb.z, tb.z));
            w.w = __float_as_uint(bce_loss(pb.w, tb.w));
            s4[i + stride] = w;
            ballot_count(w.x, true, 26, e, cnt);
            ballot_count(w.y, true, 26, e, cnt);
            ballot_count(w.z, true, 26, e, cnt);
            ballot_count(w.w, true, 26, e, cnt);
        }
    }

    if (cnt) atomicAdd(&sh[lane], cnt);
    __syncthreads();
    if (threadIdx.x < 32) {
        uint32_t c = sh[threadIdx.x];
        if (c) atomicAdd(&g_cnt[0][threadIdx.x], c);
    }
}

// ---------------------------------------------------------------------------
// K2/K3/K4: counting passes over scratch. DONE = completed levels.
// Compares bits[30 : 31-5*DONE] against the prefix (recomputed per block by
// warp 0), counts the next 5 bits. SUM=true also accumulates the exact sum
// of all elements strictly above the current bucket.
// ---------------------------------------------------------------------------
template <int DONE, bool SUM>
__global__ void __launch_bounds__(TPB) kcount() {
    __shared__ uint32_t sh[32];
    __shared__ float    wp[32];
    __shared__ uint32_t s_prefix;

    if (threadIdx.x < 32) {
        sh[threadIdx.x] = 0u;
        uint32_t prefix, kr, lb;
        chain(DONE, threadIdx.x, prefix, kr, lb);
        if (threadIdx.x == 0) s_prefix = prefix;
    }
    __syncthreads();

    const uint32_t prefix = s_prefix;
    const int cmpShift = 31 - 5 * DONE;   // 26, 21, 16
    const int balShift = cmpShift - 5;    // 21, 16, 11
    const uint32_t lane = threadIdx.x & 31u;
    const LaneMasks e = make_masks(lane);
    uint32_t cnt = 0;
    float fs = 0.0f;

    int tid = blockIdx.x * TPB + threadIdx.x;
    const int stride = GRID_BIG * TPB;
    const uint4* s4 = (const uint4*)g_scratch;

    for (int i = tid; i < N_VEC; i += 2 * stride) {
        uint4 a = s4[i];
        bool sec = (i + stride) < N_VEC;
        uint4 b;
        if (sec) b = s4[i + stride];

        {
            uint32_t v;
            v = a.x; ballot_count(v, (v >> cmpShift) == prefix, balShift, e, cnt);
            if (SUM && (v >> cmpShift) > prefix) fs += __uint_as_float(v);
            v = a.y; ballot_count(v, (v >> cmpShift) == prefix, balShift, e, cnt);
            if (SUM && (v >> cmpShift) > prefix) fs += __uint_as_float(v);
            v = a.z; ballot_count(v, (v >> cmpShift) == prefix, balShift, e, cnt);
            if (SUM && (v >> cmpShift) > prefix) fs += __uint_as_float(v);
            v = a.w; ballot_count(v, (v >> cmpShift) == prefix, balShift, e, cnt);
            if (SUM && (v >> cmpShift) > prefix) fs += __uint_as_float(v);
        }
        if (sec) {
            uint32_t v;
            v = b.x; ballot_count(v, (v >> cmpShift) == prefix, balShift, e, cnt);
            if (SUM && (v >> cmpShift) > prefix) fs += __uint_as_float(v);
            v = b.y; ballot_count(v, (v >> cmpShift) == prefix, balShift, e, cnt);
            if (SUM && (v >> cmpShift) > prefix) fs += __uint_as_float(v);
            v = b.z; ballot_count(v, (v >> cmpShift) == prefix, balShift, e, cnt);
            if (SUM && (v >> cmpShift) > prefix) fs += __uint_as_float(v);
            v = b.w; ballot_count(v, (v >> cmpShift) == prefix, balShift, e, cnt);
            if (SUM && (v >> cmpShift) > prefix) fs += __uint_as_float(v);
        }
    }

    if (cnt) atomicAdd(&sh[lane], cnt);
    if (SUM) {
#pragma unroll
        for (int o = 16; o; o >>= 1) fs += __shfl_down_sync(FULL, fs, o);
        if (lane == 0) wp[threadIdx.x >> 5] = fs;
    }
    __syncthreads();
    if (threadIdx.x < 32) {
        uint32_t c = sh[threadIdx.x];
        if (c) atomicAdd(&g_cnt[DONE][threadIdx.x], c);
        if (SUM && threadIdx.x == 0) {
            double d = 0.0;
#pragma unroll
            for (int i = 0; i < 32; i++) d += (double)wp[i];
            atomicAdd(&g_sumAbove, d);
        }
    }
}

// ---------------------------------------------------------------------------
// K5: one warp. Replay all 4 picks, handle the tie sub-bin at its midpoint
// (width 2^11 ulps ~ 2^-12 relative: error << 1e-3), write the mean.
// ---------------------------------------------------------------------------
__global__ void kfinal(float* __restrict__ out) {
    uint32_t lane = threadIdx.x;
    uint32_t prefix, kr, b4;
    chain(4, lane, prefix, kr, b4);        // kr = elements needed from sub-bin b4
    uint32_t p15 = prefix >> 5;

    uint32_t c = g_cnt[3][lane];
    uint32_t midbits = (p15 << 16) | (lane << 11) | 0x400u;  // sub-bin midpoint
    double mid = (double)__uint_as_float(midbits);
    double contrib = 0.0;
    if (lane > b4)       contrib = (double)c * mid;
    else if (lane == b4) contrib = (double)kr * mid;
#pragma unroll
    for (int o = 16; o; o >>= 1) contrib += __shfl_down_sync(FULL, contrib, o);
    if (lane == 0)
        out[0] = (float)((g_sumAbove + contrib) / (double)K_SEL);
}

// ---------------------------------------------------------------------------
extern "C" void kernel_launch(void* const* d_in, const int* in_sizes, int n_in,
                              void* d_out, int out_size) {
    (void)in_sizes; (void)n_in; (void)out_size;
    const float* pred = (const float*)d_in[0];
    const float* tgt  = (const float*)d_in[1];
    float* out = (float*)d_out;

    kzero<<<1, 128>>>();
    k1_loss<<<GRID_BIG, TPB>>>(pred, tgt);
    kcount<1, false><<<GRID_BIG, TPB>>>();
    kcount<2, false><<<GRID_BIG, TPB>>>();
    kcount<3, true ><<<GRID_BIG, TPB>>>();
    kfinal<<<1, 32>>>(out);
}

// round 6
// speedup vs baseline: 3.1633x; 1.2258x over previous
#include <cuda_runtime.h>
#include <stdint.h>

// Problem constants (SHAPE = (16,1,1024,1024), RATIO = 0.25)
#define N_TOTAL   16777216
#define N_VEC     (N_TOTAL / 4)
#define K_SEL     4194304u
#define GRID_BIG  304
#define TPB       1024
#define FULL      0xFFFFFFFFu
#define NSEG      (GRID_BIG * 32)     // 9728 warp-private segments
#define SEG_CAP   1792                // >= max elements any warp can match (56*32)

// Device-global scratch (no allocation allowed; statically zero-initialized)
__device__ uint32_t g_scratch[N_TOTAL];          // loss bit patterns
__device__ uint32_t g_scratch2[NSEG * SEG_CAP];  // compacted bucket-2 elements
__device__ uint32_t g_wcnt[NSEG];                // per-warp-segment counts
__device__ uint32_t g_cnt[4][32];                // per-level 32-way radix counts
__device__ double   g_sumAbove;

// ---------------------------------------------------------------------------
__device__ __forceinline__ float bce_loss(float x, float t) {
    // max(x,0) - x*t + log1p(exp(-|x|)); always >= 0 for t in [0,1)
    float e = __expf(-fabsf(x));
    float l = fmaxf(x, 0.0f) - x * t + __logf(1.0f + e);
    return fmaxf(l, 0.0f);   // keep sign bit 0 -> uint order == float order
}

struct LaneMasks { uint32_t e0, e1, e2, e3, e4; };
__device__ __forceinline__ LaneMasks make_masks(uint32_t lane) {
    LaneMasks m;
    m.e0 = (lane & 1u)  ? 0u : FULL;
    m.e1 = (lane & 2u)  ? 0u : FULL;
    m.e2 = (lane & 4u)  ? 0u : FULL;
    m.e3 = (lane & 8u)  ? 0u : FULL;
    m.e4 = (lane & 16u) ? 0u : FULL;
    return m;
}

// Exact 32-bin count of one element-per-lane batch via 6 ballots.
// Lane L accumulates count of elements with bits[shift+4:shift]==L (inb only).
// Must be called warp-uniformly.
__device__ __forceinline__ void ballot_count(uint32_t v, bool inb, int shift,
                                             const LaneMasks& e, uint32_t& cnt) {
    unsigned bb = __ballot_sync(FULL, inb);
    unsigned b0 = __ballot_sync(FULL, inb && ((v >> (shift + 0)) & 1u));
    unsigned b1 = __ballot_sync(FULL, inb && ((v >> (shift + 1)) & 1u));
    unsigned b2 = __ballot_sync(FULL, inb && ((v >> (shift + 2)) & 1u));
    unsigned b3 = __ballot_sync(FULL, inb && ((v >> (shift + 3)) & 1u));
    unsigned b4 = __ballot_sync(FULL, inb && ((v >> (shift + 4)) & 1u));
    unsigned m = ((b0 ^ e.e0) & (b1 ^ e.e1)) &
                 ((b2 ^ e.e2) & (b3 ^ e.e3)) &
                 ((b4 ^ e.e4) & bb);
    cnt += __popc(m);
}

// Warp-parallel descending-rank bucket pick over a 32-count row.
__device__ __forceinline__ void warp_pick(const uint32_t* __restrict__ row,
                                          uint32_t kr, uint32_t lane,
                                          uint32_t& b, uint32_t& above) {
    uint32_t c = row[lane];
    uint32_t x = c;                                   // suffix inclusive scan
#pragma unroll
    for (int off = 1; off < 32; off <<= 1) {
        uint32_t y = __shfl_down_sync(FULL, x, off);
        if (lane + off < 32) x += y;
    }
    uint32_t ab = x - c;                              // sum over j > lane
    unsigned m = __ballot_sync(FULL, (ab < kr) && (ab + c >= kr));
    b = (uint32_t)(__ffs(m) - 1);
    above = __shfl_sync(FULL, ab, b);
}

// Replay `levels` bucket picks; returns 5*levels-bit prefix and residual rank.
__device__ __forceinline__ void chain(int levels, uint32_t lane,
                                      uint32_t& prefix, uint32_t& kr,
                                      uint32_t& lastB) {
    prefix = 0u; kr = K_SEL; lastB = 0u;
    for (int l = 0; l < levels; l++) {
        uint32_t b, ab;
        warp_pick(g_cnt[l], kr, lane, b, ab);
        prefix = (prefix << 5) | b;
        kr -= ab;
        lastB = b;
    }
}

// ---------------------------------------------------------------------------
// K1: compute loss, write scratch, level-1 count on bits[30:26]
// ---------------------------------------------------------------------------
__global__ void __launch_bounds__(TPB) k1_loss(const float* __restrict__ pred,
                                               const float* __restrict__ tgt) {
    __shared__ uint32_t sh[32];
    if (threadIdx.x < 32) sh[threadIdx.x] = 0u;
    __syncthreads();

    const uint32_t lane = threadIdx.x & 31u;
    const LaneMasks e = make_masks(lane);
    uint32_t cnt = 0;

    int tid = blockIdx.x * TPB + threadIdx.x;
    const int stride = GRID_BIG * TPB;
    const float4* p4 = (const float4*)pred;
    const float4* t4 = (const float4*)tgt;
    uint4* s4 = (uint4*)g_scratch;

    for (int i = tid; i < N_VEC; i += 2 * stride) {
        float4 pa = p4[i], ta = t4[i];
        bool sec = (i + stride) < N_VEC;       // warp-uniform
        float4 pb, tb;
        if (sec) { pb = p4[i + stride]; tb = t4[i + stride]; }

        uint4 u;
        u.x = __float_as_uint(bce_loss(pa.x, ta.x));
        u.y = __float_as_uint(bce_loss(pa.y, ta.y));
        u.z = __float_as_uint(bce_loss(pa.z, ta.z));
        u.w = __float_as_uint(bce_loss(pa.w, ta.w));
        s4[i] = u;
        ballot_count(u.x, true, 26, e, cnt);
        ballot_count(u.y, true, 26, e, cnt);
        ballot_count(u.z, true, 26, e, cnt);
        ballot_count(u.w, true, 26, e, cnt);

        if (sec) {
            uint4 w;
            w.x = __float_as_uint(bce_loss(pb.x, tb.x));
            w.y = __float_as_uint(bce_loss(pb.y, tb.y));
            w.z = __float_as_uint(bce_loss(pb.z, tb.z));
            w.w = __float_as_uint(bce_loss(pb.w, tb.w));
            s4[i + stride] = w;
            ballot_count(w.x, true, 26, e, cnt);
            ballot_count(w.y, true, 26, e, cnt);
            ballot_count(w.z, true, 26, e, cnt);
            ballot_count(w.w, true, 26, e, cnt);
        }
    }

    if (cnt) atomicAdd(&sh[lane], cnt);
    __syncthreads();
    if (threadIdx.x < 32) {
        uint32_t c = sh[threadIdx.x];
        if (c) atomicAdd(&g_cnt[0][threadIdx.x], c);
    }
}

// ---------------------------------------------------------------------------
// KA: count level-2 digits (bits 25:21) among bucket-1 elements; exact sum of
// elements strictly above bucket 1.
// ---------------------------------------------------------------------------
__global__ void __launch_bounds__(TPB) kA() {
    __shared__ uint32_t sh[32];
    __shared__ float    wp[32];
    __shared__ uint32_t s_b1;

    if (threadIdx.x < 32) {
        sh[threadIdx.x] = 0u;
        uint32_t prefix, kr, lb;
        chain(1, threadIdx.x, prefix, kr, lb);
        if (threadIdx.x == 0) s_b1 = prefix;
    }
    __syncthreads();

    const uint32_t b1 = s_b1;
    const uint32_t lane = threadIdx.x & 31u;
    const LaneMasks e = make_masks(lane);
    uint32_t cnt = 0;
    float fs = 0.0f;

    int tid = blockIdx.x * TPB + threadIdx.x;
    const int stride = GRID_BIG * TPB;
    const uint4* s4 = (const uint4*)g_scratch;

    for (int i = tid; i < N_VEC; i += 2 * stride) {
        uint4 a = s4[i];
        bool sec = (i + stride) < N_VEC;
        uint4 b;
        if (sec) b = s4[i + stride];

        uint32_t v;
        v = a.x; ballot_count(v, (v >> 26) == b1, 21, e, cnt);
        if ((v >> 26) > b1) fs += __uint_as_float(v);
        v = a.y; ballot_count(v, (v >> 26) == b1, 21, e, cnt);
        if ((v >> 26) > b1) fs += __uint_as_float(v);
        v = a.z; ballot_count(v, (v >> 26) == b1, 21, e, cnt);
        if ((v >> 26) > b1) fs += __uint_as_float(v);
        v = a.w; ballot_count(v, (v >> 26) == b1, 21, e, cnt);
        if ((v >> 26) > b1) fs += __uint_as_float(v);
        if (sec) {
            v = b.x; ballot_count(v, (v >> 26) == b1, 21, e, cnt);
            if ((v >> 26) > b1) fs += __uint_as_float(v);
            v = b.y; ballot_count(v, (v >> 26) == b1, 21, e, cnt);
            if ((v >> 26) > b1) fs += __uint_as_float(v);
            v = b.z; ballot_count(v, (v >> 26) == b1, 21, e, cnt);
            if ((v >> 26) > b1) fs += __uint_as_float(v);
            v = b.w; ballot_count(v, (v >> 26) == b1, 21, e, cnt);
            if ((v >> 26) > b1) fs += __uint_as_float(v);
        }
    }

    if (cnt) atomicAdd(&sh[lane], cnt);
#pragma unroll
    for (int o = 16; o; o >>= 1) fs += __shfl_down_sync(FULL, fs, o);
    if (lane == 0) wp[threadIdx.x >> 5] = fs;
    __syncthreads();
    if (threadIdx.x < 32) {
        uint32_t c = sh[threadIdx.x];
        if (c) atomicAdd(&g_cnt[1][threadIdx.x], c);
        if (threadIdx.x == 0) {
            double d = 0.0;
#pragma unroll
            for (int i = 0; i < 32; i++) d += (double)wp[i];
            atomicAdd(&g_sumAbove, d);
        }
    }
}

// ---------------------------------------------------------------------------
// KB: compact bucket-2 elements into warp-private segments (no atomics) and
// sum elements in bucket 1 strictly above bucket 2.
// ---------------------------------------------------------------------------
__global__ void __launch_bounds__(TPB) kB() {
    __shared__ uint32_t s_p10;
    __shared__ float    wp[32];
    if (threadIdx.x < 32) {
        uint32_t prefix, kr, lb;
        chain(2, threadIdx.x, prefix, kr, lb);
        if (threadIdx.x == 0) s_p10 = prefix;
    }
    __syncthreads();

    const uint32_t p10   = s_p10;
    const uint32_t lim10 = ((p10 >> 5) << 5) + 32u;  // end of bucket-1 range at 10 bits
    const uint32_t lane  = threadIdx.x & 31u;
    const uint32_t lt    = (1u << lane) - 1u;
    const uint32_t seg   = blockIdx.x * 32u + (threadIdx.x >> 5);
    uint32_t wbase = seg * SEG_CAP;                  // write cursor (warp-uniform)
    const uint32_t wstart = wbase;
    float fs = 0.0f;

    int tid = blockIdx.x * TPB + threadIdx.x;
    const int stride = GRID_BIG * TPB;
    const uint4* s4 = (const uint4*)g_scratch;

#define KB_PROC(VV) do {                                            \
        uint32_t _v = (VV);                                         \
        uint32_t _u = _v >> 21;                                     \
        bool _match = (_u == p10);                                  \
        if (_u > p10 && _u < lim10) fs += __uint_as_float(_v);      \
        unsigned _mm = __ballot_sync(FULL, _match);                 \
        if (_match) g_scratch2[wbase + __popc(_mm & lt)] = _v;      \
        wbase += __popc(_mm);                                       \
    } while (0)

    for (int i = tid; i < N_VEC; i += 2 * stride) {
        uint4 a = s4[i];
        bool sec = (i + stride) < N_VEC;               // warp-uniform
        uint4 b;
        if (sec) b = s4[i + stride];
        KB_PROC(a.x); KB_PROC(a.y); KB_PROC(a.z); KB_PROC(a.w);
        if (sec) { KB_PROC(b.x); KB_PROC(b.y); KB_PROC(b.z); KB_PROC(b.w); }
    }
#undef KB_PROC

    if (lane == 0) g_wcnt[seg] = wbase - wstart;
#pragma unroll
    for (int o = 16; o; o >>= 1) fs += __shfl_down_sync(FULL, fs, o);
    if (lane == 0) wp[threadIdx.x >> 5] = fs;
    __syncthreads();
    if (threadIdx.x == 0) {
        double d = 0.0;
#pragma unroll
        for (int i = 0; i < 32; i++) d += (double)wp[i];
        atomicAdd(&g_sumAbove, d);
    }
}

// ---------------------------------------------------------------------------
// KC1: level-3 counts (bits 20:16) over compacted bucket-2 elements.
// One warp per segment; 304x1024 = exactly NSEG warps.
// ---------------------------------------------------------------------------
__global__ void __launch_bounds__(TPB) kC1() {
    __shared__ uint32_t sh[32];
    if (threadIdx.x < 32) sh[threadIdx.x] = 0u;
    __syncthreads();

    const uint32_t lane = threadIdx.x & 31u;
    const LaneMasks e = make_masks(lane);
    const uint32_t seg  = blockIdx.x * 32u + (threadIdx.x >> 5);
    const uint32_t n    = g_wcnt[seg];
    const uint32_t base = seg * SEG_CAP;
    uint32_t cnt = 0;

    for (uint32_t j = 0; j < n; j += 32) {            // warp-uniform trip count
        bool valid = (j + lane) < n;
        uint32_t v = valid ? g_scratch2[base + j + lane] : 0u;
        ballot_count(v, valid, 16, e, cnt);
    }

    if (cnt) atomicAdd(&sh[lane], cnt);
    __syncthreads();
    if (threadIdx.x < 32) {
        uint32_t c = sh[threadIdx.x];
        if (c) atomicAdd(&g_cnt[2][threadIdx.x], c);
    }
}

// ---------------------------------------------------------------------------
// KC2: level-4 counts (bits 15:11) within bucket 3 + exact sum of compacted
// elements strictly above bucket 3.
// ---------------------------------------------------------------------------
__global__ void __launch_bounds__(TPB) kC2() {
    __shared__ uint32_t sh[32];
    __shared__ float    wp[32];
    __shared__ uint32_t s_p15;
    if (threadIdx.x < 32) {
        sh[threadIdx.x] = 0u;
        uint32_t prefix, kr, lb;
        chain(3, threadIdx.x, prefix, kr, lb);
        if (threadIdx.x == 0) s_p15 = prefix;
    }
    __syncthreads();

    const uint32_t p15  = s_p15;
    const uint32_t lane = threadIdx.x & 31u;
    const LaneMasks e = make_masks(lane);
    const uint32_t seg  = blockIdx.x * 32u + (threadIdx.x >> 5);
    const uint32_t n    = g_wcnt[seg];
    const uint32_t base = seg * SEG_CAP;
    uint32_t cnt = 0;
    float fs = 0.0f;

    for (uint32_t j = 0; j < n; j += 32) {
        bool valid = (j + lane) < n;
        uint32_t v = valid ? g_scratch2[base + j + lane] : 0u;
        uint32_t u = v >> 16;
        ballot_count(v, valid && (u == p15), 11, e, cnt);
        if (valid && u > p15) fs += __uint_as_float(v);
    }

    if (cnt) atomicAdd(&sh[lane], cnt);
#pragma unroll
    for (int o = 16; o; o >>= 1) fs += __shfl_down_sync(FULL, fs, o);
    if (lane == 0) wp[threadIdx.x >> 5] = fs;
    __syncthreads();
    if (threadIdx.x < 32) {
        uint32_t c = sh[threadIdx.x];
        if (c) atomicAdd(&g_cnt[3][threadIdx.x], c);
        if (threadIdx.x == 0) {
            double d = 0.0;
#pragma unroll
            for (int i = 0; i < 32; i++) d += (double)wp[i];
            atomicAdd(&g_sumAbove, d);
        }
    }
}

// ---------------------------------------------------------------------------
// kfinal: replay the 4 picks, tie sub-bin at midpoint (width 2^11 ulps,
// ~2^-12 relative -> error << 1e-3), write mean, then re-zero state for the
// next graph replay.
// ---------------------------------------------------------------------------
__global__ void kfinal(float* __restrict__ out) {
    if (threadIdx.x < 32) {
        uint32_t lane = threadIdx.x;
        uint32_t prefix, kr, b4;
        chain(4, lane, prefix, kr, b4);      // kr = elements needed from tie bin
        uint32_t p15 = prefix >> 5;

        uint32_t c = g_cnt[3][lane];
        uint32_t midbits = (p15 << 16) | (lane << 11) | 0x400u;
        double mid = (double)__uint_as_float(midbits);
        double contrib = 0.0;
        if (lane > b4)       contrib = (double)c * mid;
        else if (lane == b4) contrib = (double)kr * mid;
#pragma unroll
        for (int o = 16; o; o >>= 1) contrib += __shfl_down_sync(FULL, contrib, o);
        if (lane == 0)
            out[0] = (float)((g_sumAbove + contrib) / (double)K_SEL);
    }
    __syncthreads();
    // Re-zero state for the next replay (reads above are complete).
    int t = threadIdx.x;
    if (t < 128) ((uint32_t*)g_cnt)[t] = 0u;
    if (t == 0)  g_sumAbove = 0.0;
}

// ---------------------------------------------------------------------------
extern "C" void kernel_launch(void* const* d_in, const int* in_sizes, int n_in,
                              void* d_out, int out_size) {
    (void)in_sizes; (void)n_in; (void)out_size;
    const float* pred = (const float*)d_in[0];
    const float* tgt  = (const float*)d_in[1];
    float* out = (float*)d_out;

    k1_loss<<<GRID_BIG, TPB>>>(pred, tgt);
    kA<<<GRID_BIG, TPB>>>();
    kB<<<GRID_BIG, TPB>>>();
    kC1<<<GRID_BIG, TPB>>>();
    kC2<<<GRID_BIG, TPB>>>();
    kfinal<<<1, 128>>>(out);
}

// round 7
// speedup vs baseline: 5.3221x; 1.6824x over previous
#include <cuda_runtime.h>
#include <stdint.h>

// Problem constants (SHAPE = (16,1,1024,1024), RATIO = 0.25)
#define N_TOTAL   16777216
#define N_VEC     (N_TOTAL / 4)
#define K_SEL     4194304u
#define GRID_BIG  304
#define TPB       1024
#define FULL      0xFFFFFFFFu
#define NSEG      (GRID_BIG * 32)   // 9728 warp-private segments
#define SEG_CAP   1792              // hard bound: 56 batches * 32 lanes per warp
#define HBINS     8192              // sample histogram bins = bits[30:18]
#define S_BLOCKS  64                // sample kernel grid (64*2048 = 131072 samples)
#define R_HI      29760u            // sample-rank (from top) defining T_hi (K_s - 19sigma)
#define R_LO      35776u            // sample-rank defining T_lo (K_s + 19sigma)

// Device-global state (no allocation allowed; statically zero-initialized)
__device__ __align__(16) uint32_t g_hist[HBINS];
__device__ uint32_t g_scratch2[NSEG * SEG_CAP];  // compacted window elements
__device__ uint32_t g_wcnt[NSEG];                // per-segment counts
__device__ uint32_t g_cnt[3][32];                // 3-level radix counts
__device__ uint32_t g_Tlo, g_Thi;                // window bit patterns
__device__ uint32_t g_cntAbove;                  // # elements >= T_hi
__device__ double   g_sum;                       // exact sum accumulator

// ---------------------------------------------------------------------------
__device__ __forceinline__ float bce_loss(float x, float t) {
    // max(x,0) - x*t + log1p(exp(-|x|)); always >= 0 for t in [0,1)
    float e = __expf(-fabsf(x));
    float l = fmaxf(x, 0.0f) - x * t + __logf(1.0f + e);
    return fmaxf(l, 0.0f);   // keep sign bit 0 -> uint order == float order
}

struct LaneMasks { uint32_t e0, e1, e2, e3, e4; };
__device__ __forceinline__ LaneMasks make_masks(uint32_t lane) {
    LaneMasks m;
    m.e0 = (lane & 1u)  ? 0u : FULL;
    m.e1 = (lane & 2u)  ? 0u : FULL;
    m.e2 = (lane & 4u)  ? 0u : FULL;
    m.e3 = (lane & 8u)  ? 0u : FULL;
    m.e4 = (lane & 16u) ? 0u : FULL;
    return m;
}

// Exact 32-bin count via 6 ballots; lane L accumulates count of elements with
// bits[shift+4:shift]==L among inb lanes. Warp-uniform call required.
__device__ __forceinline__ void ballot_count(uint32_t v, bool inb, int shift,
                                             const LaneMasks& e, uint32_t& cnt) {
    unsigned bb = __ballot_sync(FULL, inb);
    unsigned b0 = __ballot_sync(FULL, inb && ((v >> (shift + 0)) & 1u));
    unsigned b1 = __ballot_sync(FULL, inb && ((v >> (shift + 1)) & 1u));
    unsigned b2 = __ballot_sync(FULL, inb && ((v >> (shift + 2)) & 1u));
    unsigned b3 = __ballot_sync(FULL, inb && ((v >> (shift + 3)) & 1u));
    unsigned b4 = __ballot_sync(FULL, inb && ((v >> (shift + 4)) & 1u));
    unsigned m = ((b0 ^ e.e0) & (b1 ^ e.e1)) &
                 ((b2 ^ e.e2) & (b3 ^ e.e3)) &
                 ((b4 ^ e.e4) & bb);
    cnt += __popc(m);
}

// Warp-parallel descending-rank bucket pick over a 32-count row.
__device__ __forceinline__ void warp_pick(const uint32_t* __restrict__ row,
                                          uint32_t kr, uint32_t lane,
                                          uint32_t& b, uint32_t& above) {
    uint32_t c = row[lane];
    uint32_t x = c;                                   // suffix inclusive scan
#pragma unroll
    for (int off = 1; off < 32; off <<= 1) {
        uint32_t y = __shfl_down_sync(FULL, x, off);
        if (lane + off < 32) x += y;
    }
    uint32_t ab = x - c;                              // sum over j > lane
    unsigned m = __ballot_sync(FULL, (ab < kr) && (ab + c >= kr));
    b = (uint32_t)(__ffs(m) - 1);
    above = __shfl_sync(FULL, ab, b);
}

// Window radix parameters: b = highest bit where window values can differ;
// all compacted v share bits [31:b+1] == pfx0. Levels count [b:b-4],[b-5:b-9],
// [b-10:b-14]; tie bin = bits below b-14.
__device__ __forceinline__ void win_params(uint32_t& pfx0, int& s1) {
    uint32_t Tlo = g_Tlo, Thi = g_Thi;
    uint32_t m = Tlo ^ (Thi - 1u);
    int b = m ? (31 - __clz((int)m)) : 14;
    if (b < 14) b = 14;
    s1 = b - 4;
    pfx0 = Tlo >> (b + 1);
}

// Replay `levels` picks; prefix accumulates pfx0 then 5 bits per level.
__device__ __forceinline__ void chainW(int levels, uint32_t lane, uint32_t pfx0,
                                       uint32_t& prefix, uint32_t& kr,
                                       uint32_t& lastB) {
    prefix = pfx0; kr = K_SEL - g_cntAbove; lastB = 0u;
    for (int l = 0; l < levels; l++) {
        uint32_t b, ab;
        warp_pick(g_cnt[l], kr, lane, b, ab);
        prefix = (prefix << 5) | b;
        kr -= ab;
        lastB = b;
    }
}

// ---------------------------------------------------------------------------
// ksample: BCE on first 131072 elements -> 8192-bin histogram of bits[30:18]
// ---------------------------------------------------------------------------
__global__ void __launch_bounds__(TPB) ksample(const float* __restrict__ pred,
                                               const float* __restrict__ tgt) {
    __shared__ uint32_t sh[HBINS];
    for (int i = threadIdx.x; i < HBINS; i += TPB) sh[i] = 0u;
    __syncthreads();
    int i0 = blockIdx.x * 2048 + threadIdx.x;
#pragma unroll
    for (int r = 0; r < 2; r++) {
        int i = i0 + r * 1024;
        float l = bce_loss(pred[i], tgt[i]);
        atomicAdd(&sh[__float_as_uint(l) >> 18], 1u);
    }
    __syncthreads();
    for (int i = threadIdx.x; i < HBINS; i += TPB) {
        uint32_t c = sh[i];
        if (c) atomicAdd(&g_hist[i], c);
    }
}

// ---------------------------------------------------------------------------
// kmain: (A) every block derives [T_lo,T_hi) from the sample histogram;
// (B) single full pass: exact sum/count of v>=T_hi, compact window elements
// into warp-private segments (zero atomics in the hot loop).
// ---------------------------------------------------------------------------
__global__ void __launch_bounds__(TPB) kmain(const float* __restrict__ pred,
                                             const float* __restrict__ tgt) {
    __shared__ uint32_t sscan[TPB];
    __shared__ uint32_t s_Tlo, s_Thi;
    __shared__ float    wp[32];
    __shared__ uint32_t wc[32];
    const int t = threadIdx.x;

    // --- Phase A: window selection (redundant per block, ~2us) ---
    uint4 h0 = ((const uint4*)g_hist)[t * 2];
    uint4 h1 = ((const uint4*)g_hist)[t * 2 + 1];
    uint32_t hb[8] = {h0.x, h0.y, h0.z, h0.w, h1.x, h1.y, h1.z, h1.w};
    uint32_t part = 0;
#pragma unroll
    for (int j = 0; j < 8; j++) part += hb[j];
    sscan[t] = part;
    __syncthreads();
    for (int off = 1; off < TPB; off <<= 1) {       // inclusive suffix scan
        uint32_t v = (t + off < TPB) ? sscan[t + off] : 0u;
        __syncthreads();
        sscan[t] += v;
        __syncthreads();
    }
    uint32_t tail = sscan[t] - part;                // strictly-above count
    for (int j = 7; j >= 0; j--) {                  // bins high -> low
        uint32_t C = tail, h = hb[j];
        if (C < R_HI && C + h >= R_HI) s_Thi = ((uint32_t)(t * 8 + j) + 1u) << 18;
        if (C < R_LO && C + h >= R_LO) s_Tlo = ((uint32_t)(t * 8 + j)) << 18;
        tail += h;
    }
    __syncthreads();
    const uint32_t Tlo = s_Tlo, Thi = s_Thi;
    if (blockIdx.x == 0 && t == 0) { g_Tlo = Tlo; g_Thi = Thi; }

    // --- Phase B: main pass ---
    const uint32_t lane = t & 31u;
    const uint32_t lt   = (1u << lane) - 1u;
    const uint32_t seg  = blockIdx.x * 32u + (t >> 5);
    uint32_t wbase = seg * SEG_CAP;
    const uint32_t wstart = wbase;
    float fs = 0.0f;
    uint32_t ch = 0;

    int tid = blockIdx.x * TPB + t;
    const int stride = GRID_BIG * TPB;
    const float4* p4 = (const float4*)pred;
    const float4* t4 = (const float4*)tgt;

#define KM_PROC(PX, TX) do {                                          \
        uint32_t _v = __float_as_uint(bce_loss((PX), (TX)));          \
        bool _hi = _v >= Thi;                                         \
        if (_hi) { fs += __uint_as_float(_v); ch++; }                 \
        bool _w = (_v >= Tlo) && !_hi;                                \
        unsigned _mm = __ballot_sync(FULL, _w);                       \
        if (_w) g_scratch2[wbase + __popc(_mm & lt)] = _v;            \
        wbase += __popc(_mm);                                         \
    } while (0)

    for (int i = tid; i < N_VEC; i += 2 * stride) {   // warp-uniform guards
        float4 pa = p4[i], ta = t4[i];
        bool sec = (i + stride) < N_VEC;
        float4 pb, tb;
        if (sec) { pb = p4[i + stride]; tb = t4[i + stride]; }
        KM_PROC(pa.x, ta.x); KM_PROC(pa.y, ta.y);
        KM_PROC(pa.z, ta.z); KM_PROC(pa.w, ta.w);
        if (sec) {
            KM_PROC(pb.x, tb.x); KM_PROC(pb.y, tb.y);
            KM_PROC(pb.z, tb.z); KM_PROC(pb.w, tb.w);
        }
    }
#undef KM_PROC

    if (lane == 0) g_wcnt[seg] = wbase - wstart;
#pragma unroll
    for (int o = 16; o; o >>= 1) {
        fs += __shfl_down_sync(FULL, fs, o);
        ch += __shfl_down_sync(FULL, ch, o);
    }
    if (lane == 0) { wp[t >> 5] = fs; wc[t >> 5] = ch; }
    __syncthreads();
    if (t == 0) {
        double d = 0.0; uint32_t c = 0;
#pragma unroll
        for (int i = 0; i < 32; i++) { d += (double)wp[i]; c += wc[i]; }
        atomicAdd(&g_sum, d);
        atomicAdd(&g_cntAbove, c);
    }
}

// ---------------------------------------------------------------------------
// kr1: level-1 counts (bits [b:b-4]) over compacted; one warp per segment.
// ---------------------------------------------------------------------------
__global__ void __launch_bounds__(TPB) kr1() {
    __shared__ uint32_t sh[32];
    if (threadIdx.x < 32) sh[threadIdx.x] = 0u;
    __syncthreads();
    uint32_t pfx0; int s1; win_params(pfx0, s1);
    const uint32_t lane = threadIdx.x & 31u;
    const LaneMasks e = make_masks(lane);
    const uint32_t seg  = blockIdx.x * 32u + (threadIdx.x >> 5);
    const uint32_t n    = g_wcnt[seg];
    const uint32_t base = seg * SEG_CAP;
    uint32_t cnt = 0;
    for (uint32_t j = 0; j < n; j += 32) {
        bool valid = (j + lane) < n;
        uint32_t v = valid ? g_scratch2[base + j + lane] : 0u;
        ballot_count(v, valid, s1, e, cnt);
    }
    if (cnt) atomicAdd(&sh[lane], cnt);
    __syncthreads();
    if (threadIdx.x < 32) {
        uint32_t c = sh[threadIdx.x];
        if (c) atomicAdd(&g_cnt[0][threadIdx.x], c);
    }
}

// ---------------------------------------------------------------------------
// kr2: level-2 counts (bits [b-5:b-9]) conditional on level-1 bucket.
// ---------------------------------------------------------------------------
__global__ void __launch_bounds__(TPB) kr2() {
    __shared__ uint32_t sh[32];
    __shared__ uint32_t s_p1;
    uint32_t pfx0; int s1; win_params(pfx0, s1);
    if (threadIdx.x < 32) {
        sh[threadIdx.x] = 0u;
        uint32_t prefix, kr, lb;
        chainW(1, threadIdx.x, pfx0, prefix, kr, lb);
        if (threadIdx.x == 0) s_p1 = prefix;
    }
    __syncthreads();
    const uint32_t p1 = s_p1;
    const uint32_t lane = threadIdx.x & 31u;
    const LaneMasks e = make_masks(lane);
    const uint32_t seg  = blockIdx.x * 32u + (threadIdx.x >> 5);
    const uint32_t n    = g_wcnt[seg];
    const uint32_t base = seg * SEG_CAP;
    uint32_t cnt = 0;
    for (uint32_t j = 0; j < n; j += 32) {
        bool valid = (j + lane) < n;
        uint32_t v = valid ? g_scratch2[base + j + lane] : 0u;
        ballot_count(v, valid && ((v >> s1) == p1), s1 - 5, e, cnt);
    }
    if (cnt) atomicAdd(&sh[lane], cnt);
    __syncthreads();
    if (threadIdx.x < 32) {
        uint32_t c = sh[threadIdx.x];
        if (c) atomicAdd(&g_cnt[1][threadIdx.x], c);
    }
}

// ---------------------------------------------------------------------------
// kr3: level-3 counts (bits [b-10:b-14]) conditional on level-2 prefix, plus
// exact sum of compacted elements strictly above the level-2 bucket.
// ---------------------------------------------------------------------------
__global__ void __launch_bounds__(TPB) kr3() {
    __shared__ uint32_t sh[32];
    __shared__ float    wp[32];
    __shared__ uint32_t s_p2;
    uint32_t pfx0; int s1; win_params(pfx0, s1);
    if (threadIdx.x < 32) {
        sh[threadIdx.x] = 0u;
        uint32_t prefix, kr, lb;
        chainW(2, threadIdx.x, pfx0, prefix, kr, lb);
        if (threadIdx.x == 0) s_p2 = prefix;
    }
    __syncthreads();
    const uint32_t p2 = s_p2;
    const int s2 = s1 - 5;
    const uint32_t lane = threadIdx.x & 31u;
    const LaneMasks e = make_masks(lane);
    const uint32_t seg  = blockIdx.x * 32u + (threadIdx.x >> 5);
    const uint32_t n    = g_wcnt[seg];
    const uint32_t base = seg * SEG_CAP;
    uint32_t cnt = 0;
    float fs = 0.0f;
    for (uint32_t j = 0; j < n; j += 32) {
        bool valid = (j + lane) < n;
        uint32_t v = valid ? g_scratch2[base + j + lane] : 0u;
        uint32_t u = v >> s2;
        ballot_count(v, valid && (u == p2), s2 - 5, e, cnt);
        if (valid && u > p2) fs += __uint_as_float(v);
    }
    if (cnt) atomicAdd(&sh[lane], cnt);
#pragma unroll
    for (int o = 16; o; o >>= 1) fs += __shfl_down_sync(FULL, fs, o);
    if (lane == 0) wp[threadIdx.x >> 5] = fs;
    __syncthreads();
    if (threadIdx.x < 32) {
        uint32_t c = sh[threadIdx.x];
        if (c) atomicAdd(&g_cnt[2][threadIdx.x], c);
        if (threadIdx.x == 0) {
            double d = 0.0;
#pragma unroll
            for (int i = 0; i < 32; i++) d += (double)wp[i];
            atomicAdd(&g_sum, d);
        }
    }
}

// ---------------------------------------------------------------------------
// kfin: final pick + midpoint ties (bin width 2^(b-14) ulps, ~2^-16 relative
// for typical windows), write mean; re-zero all state for next graph replay.
// ---------------------------------------------------------------------------
__global__ void __launch_bounds__(TPB) kfin(float* __restrict__ out) {
    if (threadIdx.x < 32) {
        uint32_t pfx0; int s1; win_params(pfx0, s1);
        const int s3 = s1 - 10;                       // >= 0 by construction
        uint32_t lane = threadIdx.x;
        uint32_t prefix3, kr, b3;
        chainW(3, lane, pfx0, prefix3, kr, b3);       // kr = needed from tie bin
        uint32_t p2 = prefix3 >> 5;

        uint32_t c = g_cnt[2][lane];
        uint32_t bits = (((p2 << 5) | lane) << s3) | (s3 ? (1u << (s3 - 1)) : 0u);
        double mid = (double)__uint_as_float(bits);
        double contrib = 0.0;
        if (lane > b3)       contrib = (double)c * mid;
        else if (lane == b3) contrib = (double)kr * mid;
#pragma unroll
        for (int o = 16; o; o >>= 1) contrib += __shfl_down_sync(FULL, contrib, o);
        if (lane == 0)
            out[0] = (float)((g_sum + contrib) / (double)K_SEL);
    }
    __syncthreads();
    // Re-zero state for the next replay.
    int t = threadIdx.x;
    for (int i = t; i < HBINS; i += TPB) g_hist[i] = 0u;
    if (t < 96) ((uint32_t*)g_cnt)[t] = 0u;
    if (t == 0) { g_sum = 0.0; g_cntAbove = 0u; }
}

// ---------------------------------------------------------------------------
extern "C" void kernel_launch(void* const* d_in, const int* in_sizes, int n_in,
                              void* d_out, int out_size) {
    (void)in_sizes; (void)n_in; (void)out_size;
    const float* pred = (const float*)d_in[0];
    const float* tgt  = (const float*)d_in[1];
    float* out = (float*)d_out;

    ksample<<<S_BLOCKS, TPB>>>(pred, tgt);
    kmain<<<GRID_BIG, TPB>>>(pred, tgt);
    kr1<<<GRID_BIG, TPB>>>();
    kr2<<<GRID_BIG, TPB>>>();
    kr3<<<GRID_BIG, TPB>>>();
    kfin<<<1, TPB>>>(out);
}